// round 1
// baseline (speedup 1.0000x reference)
#include <cuda_runtime.h>
#include <math.h>

#define E_   8
#define M_   1024
#define H_   4096
#define SMAX 16384
#define CAP  2048

// ---------------- device scratch (allocation-free rule: __device__ globals) ---
__device__ int   g_idx[SMAX];
__device__ float g_gate[SMAX];
__device__ float g_gate_sums[E_];
__device__ int   g_counts[E_];
__device__ int   g_kept[E_];
__device__ int   g_slot_token[E_ * CAP];
__device__ float g_slot_gate[E_ * CAP];
__device__ float g_h[(size_t)E_ * CAP * H_];   // 256 MB intermediate activations

// ---------------- init: zero per-launch accumulators --------------------------
__global__ void init_kernel() {
    int t = threadIdx.x;
    if (t < E_) g_gate_sums[t] = 0.0f;
}

// ---------------- gating: logits -> softmax -> argmax -------------------------
// one warp per token; 8 warps per block; wg staged in shared (32 KB)
__global__ __launch_bounds__(256) void gate_kernel(const float* __restrict__ x,
                                                   const float* __restrict__ wg,
                                                   int s) {
    __shared__ float swg[M_ * E_];
    __shared__ float bsum[E_];
    int tid = threadIdx.x;
    for (int i = tid; i < M_ * E_; i += 256) swg[i] = wg[i];
    if (tid < E_) bsum[tid] = 0.0f;
    __syncthreads();

    int warp = tid >> 5, lane = tid & 31;
    int tok = blockIdx.x * 8 + warp;
    if (tok < s) {
        const float* xr = x + (size_t)tok * M_;
        float acc[E_];
#pragma unroll
        for (int e = 0; e < E_; e++) acc[e] = 0.0f;
        for (int k = lane; k < M_; k += 32) {
            float xv = xr[k];
#pragma unroll
            for (int e = 0; e < E_; e++) acc[e] += xv * swg[k * E_ + e];
        }
#pragma unroll
        for (int off = 16; off; off >>= 1) {
#pragma unroll
            for (int e = 0; e < E_; e++)
                acc[e] += __shfl_down_sync(0xffffffffu, acc[e], off);
        }
        if (lane == 0) {
            float mx = acc[0]; int am = 0;
#pragma unroll
            for (int e = 1; e < E_; e++) if (acc[e] > mx) { mx = acc[e]; am = e; }
            float g[E_]; float sum = 0.0f;
#pragma unroll
            for (int e = 0; e < E_; e++) { g[e] = expf(acc[e] - mx); sum += g[e]; }
            float inv = 1.0f / sum;
            g_idx[tok]  = am;
            g_gate[tok] = g[am] * inv;
#pragma unroll
            for (int e = 0; e < E_; e++) atomicAdd(&bsum[e], g[e] * inv);
        }
    }
    __syncthreads();
    if (tid < E_) atomicAdd(&g_gate_sums[tid], bsum[tid]);
}

// ---------------- routing scan: token-order ranks, capacity drop, tail --------
// single block; deterministic order-preserving cumsum per expert
__global__ __launch_bounds__(256) void scan_kernel(int s, int capacity,
                                                   float* __restrict__ out,
                                                   long long out_size) {
    __shared__ int cnt[256][E_];
    __shared__ int totals[E_];
    int tid = threadIdx.x;
    int chunk = (s + 255) / 256;
    int lo = tid * chunk;
    int hi = lo + chunk; if (hi > s) hi = s;

    int c[E_];
#pragma unroll
    for (int e = 0; e < E_; e++) c[e] = 0;
    for (int t = lo; t < hi; t++) c[g_idx[t]]++;
#pragma unroll
    for (int e = 0; e < E_; e++) cnt[tid][e] = c[e];
    __syncthreads();

    if (tid < E_) {
        int run = 0;
        for (int i = 0; i < 256; i++) { int v = cnt[i][tid]; cnt[i][tid] = run; run += v; }
        totals[tid]   = run;
        g_counts[tid] = run;
        g_kept[tid]   = run < capacity ? run : capacity;
    }
    __syncthreads();

    int base[E_];
#pragma unroll
    for (int e = 0; e < E_; e++) base[e] = cnt[tid][e];
    for (int t = lo; t < hi; t++) {
        int e = g_idx[t];
        int loc = base[e]++;
        if (loc < capacity) {
            g_slot_token[e * capacity + loc] = t;
            g_slot_gate [e * capacity + loc] = g_gate[t];
        }
    }

    if (tid == 0 && out_size > (long long)s * M_) {
        float la = 0.0f;
        float inv_s = 1.0f / (float)s;
        for (int e = 0; e < E_; e++)
            la += (g_gate_sums[e] * inv_s) * ((float)totals[e] * inv_s);
        la *= (float)E_;
        long long off = (long long)s * M_;
        out[off] = la;
        for (int e = 0; e < E_; e++) out[off + 1 + e] = (float)totals[e];
    }
}

// ---------------- GEMM1: h = gelu(gather(x) @ w1[e] + b1[e]) ------------------
// 128x128 tile, BK=16, 8x8 per-thread, A gathered via slot_token
__global__ __launch_bounds__(256) void gemm1_kernel(const float* __restrict__ x,
                                                    const float* __restrict__ w1,
                                                    const float* __restrict__ b1,
                                                    int capacity) {
    const int e = blockIdx.z;
    const int kept = g_kept[e];
    const int m0 = blockIdx.y * 128;
    if (m0 >= kept) return;
    const int n0 = blockIdx.x * 128;

    __shared__ float As[16][128];
    __shared__ float Bs[16][128];
    __shared__ int   tok[128];

    int tid = threadIdx.x;
    if (tid < 128) {
        int r = m0 + tid;
        tok[tid] = (r < kept) ? g_slot_token[e * capacity + r] : -1;
    }
    __syncthreads();

    const float* w1e = w1 + (size_t)e * M_ * H_;
    float acc[8][8];
#pragma unroll
    for (int i = 0; i < 8; i++)
#pragma unroll
        for (int j = 0; j < 8; j++) acc[i][j] = 0.0f;

    int tx = tid & 15;   // N direction
    int ty = tid >> 4;   // M direction

    for (int k0 = 0; k0 < M_; k0 += 16) {
#pragma unroll
        for (int i = 0; i < 2; i++) {
            int slot = tid + i * 256;          // 512 float4 slots = 128 rows x 4
            int row = slot >> 2;
            int kk  = (slot & 3) * 4;
            float4 v = make_float4(0.f, 0.f, 0.f, 0.f);
            int t = tok[row];
            if (t >= 0) v = *(const float4*)(x + (size_t)t * M_ + k0 + kk);
            As[kk + 0][row] = v.x; As[kk + 1][row] = v.y;
            As[kk + 2][row] = v.z; As[kk + 3][row] = v.w;
        }
#pragma unroll
        for (int i = 0; i < 2; i++) {
            int slot = tid + i * 256;          // 512 float4 slots = 16 k x 32
            int bk = slot >> 5;
            int bn = (slot & 31) * 4;
            *(float4*)&Bs[bk][bn] =
                *(const float4*)(w1e + (size_t)(k0 + bk) * H_ + n0 + bn);
        }
        __syncthreads();
#pragma unroll
        for (int kk = 0; kk < 16; kk++) {
            float a[8], b[8];
#pragma unroll
            for (int i = 0; i < 8; i++) a[i] = As[kk][ty * 8 + i];
#pragma unroll
            for (int j = 0; j < 8; j++) b[j] = Bs[kk][tx * 8 + j];
#pragma unroll
            for (int i = 0; i < 8; i++)
#pragma unroll
                for (int j = 0; j < 8; j++) acc[i][j] += a[i] * b[j];
        }
        __syncthreads();
    }

    const float* b1e = b1 + e * H_;
#pragma unroll
    for (int i = 0; i < 8; i++) {
        int r = m0 + ty * 8 + i;
        if (r < kept) {
            float* hrow = g_h + ((size_t)e * CAP + r) * H_;
#pragma unroll
            for (int j = 0; j < 8; j++) {
                int n = n0 + tx * 8 + j;
                float v = acc[i][j] + b1e[n];
                // JAX default gelu: tanh approximation
                float u = 0.7978845608028654f * (v + 0.044715f * v * v * v);
                hrow[n] = 0.5f * v * (1.0f + tanhf(u));
            }
        }
    }
}

// ---------------- GEMM2: out[token] = (h @ w2[e] + b2[e]) * gate --------------
__global__ __launch_bounds__(256) void gemm2_kernel(const float* __restrict__ w2,
                                                    const float* __restrict__ b2,
                                                    float* __restrict__ out,
                                                    int capacity) {
    const int e = blockIdx.z;
    const int kept = g_kept[e];
    const int m0 = blockIdx.y * 128;
    if (m0 >= kept) return;
    const int n0 = blockIdx.x * 128;

    __shared__ float As[16][128];
    __shared__ float Bs[16][128];

    int tid = threadIdx.x;
    const float* w2e  = w2 + (size_t)e * H_ * M_;
    const float* hblk = g_h + ((size_t)e * CAP + m0) * H_;

    float acc[8][8];
#pragma unroll
    for (int i = 0; i < 8; i++)
#pragma unroll
        for (int j = 0; j < 8; j++) acc[i][j] = 0.0f;

    int tx = tid & 15;
    int ty = tid >> 4;

    for (int k0 = 0; k0 < H_; k0 += 16) {
#pragma unroll
        for (int i = 0; i < 2; i++) {
            int slot = tid + i * 256;
            int row = slot >> 2;
            int kk  = (slot & 3) * 4;
            // rows >= kept read stale scratch; results for them are never stored
            float4 v = *(const float4*)(hblk + (size_t)row * H_ + k0 + kk);
            As[kk + 0][row] = v.x; As[kk + 1][row] = v.y;
            As[kk + 2][row] = v.z; As[kk + 3][row] = v.w;
        }
#pragma unroll
        for (int i = 0; i < 2; i++) {
            int slot = tid + i * 256;
            int bk = slot >> 5;
            int bn = (slot & 31) * 4;
            *(float4*)&Bs[bk][bn] =
                *(const float4*)(w2e + (size_t)(k0 + bk) * M_ + n0 + bn);
        }
        __syncthreads();
#pragma unroll
        for (int kk = 0; kk < 16; kk++) {
            float a[8], b[8];
#pragma unroll
            for (int i = 0; i < 8; i++) a[i] = As[kk][ty * 8 + i];
#pragma unroll
            for (int j = 0; j < 8; j++) b[j] = Bs[kk][tx * 8 + j];
#pragma unroll
            for (int i = 0; i < 8; i++)
#pragma unroll
                for (int j = 0; j < 8; j++) acc[i][j] += a[i] * b[j];
        }
        __syncthreads();
    }

    const float* b2e = b2 + e * M_;
#pragma unroll
    for (int i = 0; i < 8; i++) {
        int r = m0 + ty * 8 + i;
        if (r < kept) {
            int t = g_slot_token[e * capacity + r];
            float gate = g_slot_gate[e * capacity + r];
            float* orow = out + (size_t)t * M_;
#pragma unroll
            for (int j = 0; j < 8; j++) {
                int n = n0 + tx * 8 + j;
                orow[n] = (acc[i][j] + b2e[n]) * gate;
            }
        }
    }
}

// ---------------- launch -------------------------------------------------------
extern "C" void kernel_launch(void* const* d_in, const int* in_sizes, int n_in,
                              void* d_out, int out_size) {
    const float* x  = (const float*)d_in[0];
    const float* wg = (const float*)d_in[1];
    const float* w1 = (const float*)d_in[2];
    const float* b1 = (const float*)d_in[3];
    const float* w2 = (const float*)d_in[4];
    const float* b2 = (const float*)d_in[5];
    float* out = (float*)d_out;

    int s = in_sizes[0] / M_;                    // tokens (16384)
    int capacity = (s + E_ - 1) / E_;            // ceil(s/E * 1.0)
    if (capacity < 4) capacity = 4;
    if (capacity > CAP) capacity = CAP;          // scratch bound (holds for this shape)

    // dropped tokens must be exactly 0; out buffer is poisoned before timing
    cudaMemsetAsync(d_out, 0, (size_t)out_size * sizeof(float), 0);

    init_kernel<<<1, 32>>>();
    gate_kernel<<<(s + 7) / 8, 256>>>(x, wg, s);
    scan_kernel<<<1, 256>>>(s, capacity, out, (long long)out_size);

    dim3 g1(H_ / 128, (capacity + 127) / 128, E_);
    gemm1_kernel<<<g1, 256>>>(x, w1, b1, capacity);

    dim3 g2(M_ / 128, (capacity + 127) / 128, E_);
    gemm2_kernel<<<g2, 256>>>(w2, b2, out, capacity);
}